// round 1
// baseline (speedup 1.0000x reference)
#include <cuda_runtime.h>

#define F_IN 512
#define HID  128
#define OUTF 40
#define MAXN 50000
#define MAXE 800000

// ---- device scratch (static; no allocation) ----
__device__ float g_xw[MAXN * HID];    // X @ W1
__device__ float g_h[MAXN * HID];     // hidden after spmm+relu+mask
__device__ float g_t2[MAXN * OUTF];   // h @ W2
__device__ int   g_counts[MAXN];
__device__ int   g_rowstart[MAXN];
__device__ int   g_cur[MAXN];
__device__ int   g_perm[MAXE];
__device__ int   g_bsums[256];

// ================= CSR build =================
__global__ void zero_counts_kernel(int M) {
    int i = blockIdx.x * blockDim.x + threadIdx.x;
    if (i < M) g_counts[i] = 0;
}

__global__ void hist_kernel(const int* __restrict__ dst, int E) {
    int e = blockIdx.x * blockDim.x + threadIdx.x;
    if (e < E) atomicAdd(&g_counts[dst[e]], 1);
}

// block-level exclusive scan (Hillis-Steele on 256)
__global__ void scanA_kernel(int M) {
    __shared__ int s[256];
    int tid = threadIdx.x;
    int i = blockIdx.x * 256 + tid;
    int v = (i < M) ? g_counts[i] : 0;
    s[tid] = v;
    __syncthreads();
    #pragma unroll
    for (int off = 1; off < 256; off <<= 1) {
        int t = (tid >= off) ? s[tid - off] : 0;
        __syncthreads();
        s[tid] += t;
        __syncthreads();
    }
    if (i < M) g_rowstart[i] = s[tid] - v;   // exclusive within block
    if (tid == 255) g_bsums[blockIdx.x] = s[255];
}

__global__ void scanB_kernel(int nb) {
    __shared__ int s[256];
    int tid = threadIdx.x;
    int v = (tid < nb) ? g_bsums[tid] : 0;
    s[tid] = v;
    __syncthreads();
    #pragma unroll
    for (int off = 1; off < 256; off <<= 1) {
        int t = (tid >= off) ? s[tid - off] : 0;
        __syncthreads();
        s[tid] += t;
        __syncthreads();
    }
    if (tid < nb) g_bsums[tid] = s[tid] - v;  // exclusive block offsets
}

__global__ void scanC_kernel(int M) {
    int i = blockIdx.x * 256 + threadIdx.x;
    if (i < M) {
        int v = g_rowstart[i] + g_bsums[blockIdx.x];
        g_rowstart[i] = v;
        g_cur[i] = v;
    }
}

__global__ void fill_perm_kernel(const int* __restrict__ dst, int E) {
    int e = blockIdx.x * blockDim.x + threadIdx.x;
    if (e < E) {
        int p = atomicAdd(&g_cur[dst[e]], 1);
        g_perm[p] = e;
    }
}

// ================= GEMM1: [M,512] @ [512,128] =================
__global__ __launch_bounds__(256) void gemm1_kernel(
    const float* __restrict__ X, const float* __restrict__ W, int M)
{
    __shared__ float As[16][128];   // [k][row] (transposed)
    __shared__ float Bs[16][128];   // [k][col]
    const int tid = threadIdx.x;
    const int tx = tid & 15;        // col group
    const int ty = tid >> 4;        // row group
    const int rowBase = blockIdx.x * 128;

    const int ar = tid >> 2;          // 0..63
    const int ak = (tid & 3) << 2;    // 0,4,8,12
    const int bk = tid >> 4;          // 0..15
    const int bn = (tid & 15) << 3;   // 0..120

    const int r0 = rowBase + ar;
    const int r1 = r0 + 64;
    const bool v0 = (r0 < M), v1 = (r1 < M);

    float acc[8][8] = {};

    for (int k0 = 0; k0 < F_IN; k0 += 16) {
        float4 a0 = v0 ? *(const float4*)(X + (size_t)r0 * F_IN + k0 + ak)
                       : make_float4(0.f, 0.f, 0.f, 0.f);
        float4 a1 = v1 ? *(const float4*)(X + (size_t)r1 * F_IN + k0 + ak)
                       : make_float4(0.f, 0.f, 0.f, 0.f);
        float4 w0 = *(const float4*)(W + (size_t)(k0 + bk) * HID + bn);
        float4 w1 = *(const float4*)(W + (size_t)(k0 + bk) * HID + bn + 4);

        As[ak + 0][ar] = a0.x; As[ak + 1][ar] = a0.y;
        As[ak + 2][ar] = a0.z; As[ak + 3][ar] = a0.w;
        As[ak + 0][ar + 64] = a1.x; As[ak + 1][ar + 64] = a1.y;
        As[ak + 2][ar + 64] = a1.z; As[ak + 3][ar + 64] = a1.w;
        *(float4*)&Bs[bk][bn]     = w0;
        *(float4*)&Bs[bk][bn + 4] = w1;
        __syncthreads();

        #pragma unroll
        for (int kk = 0; kk < 16; ++kk) {
            float a[8], b[8];
            *(float4*)&a[0] = *(const float4*)&As[kk][ty * 8];
            *(float4*)&a[4] = *(const float4*)&As[kk][ty * 8 + 4];
            *(float4*)&b[0] = *(const float4*)&Bs[kk][tx * 8];
            *(float4*)&b[4] = *(const float4*)&Bs[kk][tx * 8 + 4];
            #pragma unroll
            for (int i = 0; i < 8; ++i)
                #pragma unroll
                for (int j = 0; j < 8; ++j)
                    acc[i][j] = fmaf(a[i], b[j], acc[i][j]);
        }
        __syncthreads();
    }

    #pragma unroll
    for (int i = 0; i < 8; ++i) {
        int r = rowBase + ty * 8 + i;
        if (r < M) {
            *(float4*)(g_xw + (size_t)r * HID + tx * 8) =
                make_float4(acc[i][0], acc[i][1], acc[i][2], acc[i][3]);
            *(float4*)(g_xw + (size_t)r * HID + tx * 8 + 4) =
                make_float4(acc[i][4], acc[i][5], acc[i][6], acc[i][7]);
        }
    }
}

// ================= SpMM1 (HID=128): warp per row + fused relu/bias/mask =====
__global__ __launch_bounds__(256) void spmm1_kernel(
    const int* __restrict__ src, const float* __restrict__ ew,
    const float* __restrict__ b1, const float* __restrict__ mask, int M)
{
    int gw = (blockIdx.x * blockDim.x + threadIdx.x) >> 5;
    int lane = threadIdx.x & 31;
    if (gw >= M) return;
    int start = g_rowstart[gw];
    int deg = g_counts[gw];
    float4 acc = make_float4(0.f, 0.f, 0.f, 0.f);

    for (int base = 0; base < deg; base += 32) {
        int rem = deg - base;
        int cnt = rem < 32 ? rem : 32;
        int s = 0; float w = 0.f;
        if (lane < cnt) {
            int e = g_perm[start + base + lane];
            s = src[e];
            w = ew[e];
        }
        for (int i = 0; i < cnt; ++i) {
            int   ss = __shfl_sync(0xffffffffu, s, i);
            float ww = __shfl_sync(0xffffffffu, w, i);
            float4 v = *(const float4*)(g_xw + (size_t)ss * HID + (lane << 2));
            acc.x = fmaf(ww, v.x, acc.x);
            acc.y = fmaf(ww, v.y, acc.y);
            acc.z = fmaf(ww, v.z, acc.z);
            acc.w = fmaf(ww, v.w, acc.w);
        }
    }

    float4 b = *(const float4*)(b1 + (lane << 2));
    float4 m = *(const float4*)(mask + (size_t)gw * HID + (lane << 2));
    float4 o;
    o.x = fmaxf(acc.x + b.x, 0.f) * m.x;
    o.y = fmaxf(acc.y + b.y, 0.f) * m.y;
    o.z = fmaxf(acc.z + b.z, 0.f) * m.z;
    o.w = fmaxf(acc.w + b.w, 0.f) * m.w;
    *(float4*)(g_h + (size_t)gw * HID + (lane << 2)) = o;
}

// ================= GEMM2: [M,128] @ [128,40] =================
__global__ __launch_bounds__(256) void gemm2_kernel(const float* __restrict__ W2, int M)
{
    __shared__ float Ws[HID][OUTF];   // 20 KB
    int tid = threadIdx.x;
    for (int i = tid; i < HID * OUTF; i += 256)
        Ws[i / OUTF][i % OUTF] = W2[i];
    __syncthreads();

    int r = blockIdx.x * 64 + (tid >> 2);
    int c0 = (tid & 3) * 10;
    if (r >= M) return;

    float acc[10] = {};
    const float4* hrow = (const float4*)(g_h + (size_t)r * HID);
    #pragma unroll 4
    for (int k4 = 0; k4 < HID / 4; ++k4) {
        float4 a = hrow[k4];
        int k = k4 * 4;
        #pragma unroll
        for (int j = 0; j < 10; ++j) acc[j] = fmaf(a.x, Ws[k + 0][c0 + j], acc[j]);
        #pragma unroll
        for (int j = 0; j < 10; ++j) acc[j] = fmaf(a.y, Ws[k + 1][c0 + j], acc[j]);
        #pragma unroll
        for (int j = 0; j < 10; ++j) acc[j] = fmaf(a.z, Ws[k + 2][c0 + j], acc[j]);
        #pragma unroll
        for (int j = 0; j < 10; ++j) acc[j] = fmaf(a.w, Ws[k + 3][c0 + j], acc[j]);
    }
    float* trow = g_t2 + (size_t)r * OUTF + c0;
    #pragma unroll
    for (int j = 0; j < 10; ++j) trow[j] = acc[j];
}

// ================= SpMM2 (OUT=40): warp per row + fused b2 =================
__global__ __launch_bounds__(256) void spmm2_kernel(
    const int* __restrict__ src, const float* __restrict__ ew,
    const float* __restrict__ b2, float* __restrict__ out, int M)
{
    int gw = (blockIdx.x * blockDim.x + threadIdx.x) >> 5;
    int lane = threadIdx.x & 31;
    if (gw >= M) return;
    int start = g_rowstart[gw];
    int deg = g_counts[gw];
    float2 acc = make_float2(0.f, 0.f);

    for (int base = 0; base < deg; base += 32) {
        int rem = deg - base;
        int cnt = rem < 32 ? rem : 32;
        int s = 0; float w = 0.f;
        if (lane < cnt) {
            int e = g_perm[start + base + lane];
            s = src[e];
            w = ew[e];
        }
        for (int i = 0; i < cnt; ++i) {
            int   ss = __shfl_sync(0xffffffffu, s, i);
            float ww = __shfl_sync(0xffffffffu, w, i);
            if (lane < 20) {
                float2 v = *(const float2*)(g_t2 + (size_t)ss * OUTF + (lane << 1));
                acc.x = fmaf(ww, v.x, acc.x);
                acc.y = fmaf(ww, v.y, acc.y);
            }
        }
    }

    if (lane < 20) {
        float2 b = *(const float2*)(b2 + (lane << 1));
        float2 o = make_float2(acc.x + b.x, acc.y + b.y);
        *(float2*)(out + (size_t)gw * OUTF + (lane << 1)) = o;
    }
}

// ================= launch =================
extern "C" void kernel_launch(void* const* d_in, const int* in_sizes, int n_in,
                              void* d_out, int out_size)
{
    const float* x    = (const float*)d_in[0];
    const float* W1   = (const float*)d_in[1];
    const float* b1   = (const float*)d_in[2];
    const float* W2   = (const float*)d_in[3];
    const float* b2   = (const float*)d_in[4];
    const float* ew   = (const float*)d_in[5];
    const float* mask = (const float*)d_in[6];
    const int*   esrc = (const int*)d_in[7];
    const int*   edst = (const int*)d_in[8];
    float* out = (float*)d_out;

    const int M = in_sizes[0] / F_IN;   // 50000
    const int E = in_sizes[7];          // 800000

    const int nbM = (M + 255) / 256;    // 196
    const int nbE = (E + 255) / 256;

    // CSR build (by destination)
    zero_counts_kernel<<<nbM, 256>>>(M);
    hist_kernel<<<nbE, 256>>>(edst, E);
    scanA_kernel<<<nbM, 256>>>(M);
    scanB_kernel<<<1, 256>>>(nbM);
    scanC_kernel<<<nbM, 256>>>(M);
    fill_perm_kernel<<<nbE, 256>>>(edst, E);

    // layer 1
    gemm1_kernel<<<(M + 127) / 128, 256>>>(x, W1, M);
    spmm1_kernel<<<(M + 7) / 8, 256>>>(esrc, ew, b1, mask, M);

    // layer 2
    gemm2_kernel<<<(M + 63) / 64, 256>>>(W2, M);
    spmm2_kernel<<<(M + 7) / 8, 256>>>(esrc, ew, b2, out, M);
}

// round 4
// speedup vs baseline: 1.6627x; 1.6627x over previous
#include <cuda_runtime.h>
#include <cstdint>

#define F_IN 512
#define HID  128
#define OUTF 40
#define MAXN 50000
#define MAXE 800000

// ---- device scratch (static; no allocation) ----
__device__ float g_xw[MAXN * HID];    // X @ W1
__device__ float g_h[MAXN * HID];     // hidden after spmm+relu+mask
__device__ float g_t2[MAXN * OUTF];   // h @ W2
__device__ int   g_counts[MAXN];
__device__ int   g_rowstart[MAXN];
__device__ int   g_cur[MAXN];
__device__ int   g_perm[MAXE];
__device__ int   g_bsums[256];

// ================= CSR build =================
__global__ void zero_counts_kernel(int M) {
    int i = blockIdx.x * blockDim.x + threadIdx.x;
    if (i < M) g_counts[i] = 0;
}

__global__ void hist_kernel(const int* __restrict__ dst, int E) {
    int e = blockIdx.x * blockDim.x + threadIdx.x;
    if (e < E) atomicAdd(&g_counts[dst[e]], 1);
}

__global__ void scanA_kernel(int M) {
    __shared__ int s[256];
    int tid = threadIdx.x;
    int i = blockIdx.x * 256 + tid;
    int v = (i < M) ? g_counts[i] : 0;
    s[tid] = v;
    __syncthreads();
    #pragma unroll
    for (int off = 1; off < 256; off <<= 1) {
        int t = (tid >= off) ? s[tid - off] : 0;
        __syncthreads();
        s[tid] += t;
        __syncthreads();
    }
    if (i < M) g_rowstart[i] = s[tid] - v;
    if (tid == 255) g_bsums[blockIdx.x] = s[255];
}

__global__ void scanB_kernel(int nb) {
    __shared__ int s[256];
    int tid = threadIdx.x;
    int v = (tid < nb) ? g_bsums[tid] : 0;
    s[tid] = v;
    __syncthreads();
    #pragma unroll
    for (int off = 1; off < 256; off <<= 1) {
        int t = (tid >= off) ? s[tid - off] : 0;
        __syncthreads();
        s[tid] += t;
        __syncthreads();
    }
    if (tid < nb) g_bsums[tid] = s[tid] - v;
}

__global__ void scanC_kernel(int M) {
    int i = blockIdx.x * 256 + threadIdx.x;
    if (i < M) {
        int v = g_rowstart[i] + g_bsums[blockIdx.x];
        g_rowstart[i] = v;
        g_cur[i] = v;
    }
}

__global__ void fill_perm_kernel(const int* __restrict__ dst, int E) {
    int e = blockIdx.x * blockDim.x + threadIdx.x;
    if (e < E) {
        int p = atomicAdd(&g_cur[dst[e]], 1);
        g_perm[p] = e;
    }
}

// ================= GEMM1 (tensor cores, tf32) =================
// [M,512] @ [512,128] -> g_xw.  Block tile 128x128, 8 warps (4Mx2N), warp 32x64.
// K-chunk = 16, double-buffered smem, fp32 rounded to tf32 via cvt.rna.

__device__ __forceinline__ uint32_t f2tf(float f) {
    uint32_t u;
    asm("cvt.rna.tf32.f32 %0, %1;" : "=r"(u) : "f"(f));
    return u;
}

#define AS_STRIDE 20    // 16 k + 4 pad  (bank = (20*g + la) % 32 : permutation)
#define BS_STRIDE 136   // 128 col + 8 pad (bank = (8*la + col) % 32 : permutation)

__global__ __launch_bounds__(256, 2) void gemm1_tc_kernel(
    const float* __restrict__ X, const float* __restrict__ W, int M)
{
    __shared__ uint32_t As[2][128 * AS_STRIDE];   // [row][k]
    __shared__ uint32_t Bs[2][16 * BS_STRIDE];    // [k][col]

    const int tid  = threadIdx.x;
    const int lane = tid & 31;
    const int wid  = tid >> 5;
    const int wm   = wid >> 1;        // 0..3 -> M offset wm*32
    const int wn   = wid & 1;         // 0..1 -> N offset wn*64
    const int g    = lane >> 2;       // 0..7
    const int la   = lane & 3;        // 0..3
    const int rowBase = blockIdx.x * 128;

    const int aRow = tid >> 2;        // + i*64
    const int aC4  = tid & 3;
    const int bK   = tid >> 5;        // + i*8
    const int bC4  = tid & 31;

    float acc[2][8][4];
    #pragma unroll
    for (int mt = 0; mt < 2; ++mt)
        #pragma unroll
        for (int nt = 0; nt < 8; ++nt)
            #pragma unroll
            for (int r = 0; r < 4; ++r) acc[mt][nt][r] = 0.f;

    float4 aL[2], bL[2];

    #define LOADG(kc) {                                                          \
        _Pragma("unroll")                                                        \
        for (int i = 0; i < 2; ++i) {                                            \
            int r = rowBase + aRow + i * 64;                                     \
            aL[i] = (r < M) ? *(const float4*)(X + (size_t)r * F_IN + (kc)*16 + aC4*4) \
                            : make_float4(0.f, 0.f, 0.f, 0.f);                   \
        }                                                                        \
        _Pragma("unroll")                                                        \
        for (int i = 0; i < 2; ++i) {                                            \
            int k = (kc)*16 + bK + i * 8;                                        \
            bL[i] = *(const float4*)(W + (size_t)k * HID + bC4 * 4);             \
        }                                                                        \
    }

    #define STORES(b) {                                                          \
        _Pragma("unroll")                                                        \
        for (int i = 0; i < 2; ++i) {                                            \
            uint4 u = make_uint4(f2tf(aL[i].x), f2tf(aL[i].y),                   \
                                 f2tf(aL[i].z), f2tf(aL[i].w));                  \
            *(uint4*)&As[b][(aRow + i * 64) * AS_STRIDE + aC4 * 4] = u;          \
        }                                                                        \
        _Pragma("unroll")                                                        \
        for (int i = 0; i < 2; ++i) {                                            \
            uint4 u = make_uint4(f2tf(bL[i].x), f2tf(bL[i].y),                   \
                                 f2tf(bL[i].z), f2tf(bL[i].w));                  \
            *(uint4*)&Bs[b][(bK + i * 8) * BS_STRIDE + bC4 * 4] = u;             \
        }                                                                        \
    }

    LOADG(0);
    STORES(0);
    __syncthreads();

    const int NCHUNK = F_IN / 16;   // 32
    for (int kc = 0; kc < NCHUNK; ++kc) {
        int b = kc & 1;
        if (kc + 1 < NCHUNK) LOADG(kc + 1);

        #pragma unroll
        for (int ks = 0; ks < 2; ++ks) {
            uint32_t af[2][4], bf[8][2];
            #pragma unroll
            for (int mt = 0; mt < 2; ++mt) {
                int rb = wm * 32 + mt * 16;
                af[mt][0] = As[b][(rb + g)     * AS_STRIDE + ks * 8 + la];
                af[mt][1] = As[b][(rb + 8 + g) * AS_STRIDE + ks * 8 + la];
                af[mt][2] = As[b][(rb + g)     * AS_STRIDE + ks * 8 + la + 4];
                af[mt][3] = As[b][(rb + 8 + g) * AS_STRIDE + ks * 8 + la + 4];
            }
            #pragma unroll
            for (int nt = 0; nt < 8; ++nt) {
                int col = wn * 64 + nt * 8 + g;
                bf[nt][0] = Bs[b][(ks * 8 + la)     * BS_STRIDE + col];
                bf[nt][1] = Bs[b][(ks * 8 + la + 4) * BS_STRIDE + col];
            }
            #pragma unroll
            for (int mt = 0; mt < 2; ++mt)
                #pragma unroll
                for (int nt = 0; nt < 8; ++nt) {
                    float* c = acc[mt][nt];
                    asm volatile(
                        "mma.sync.aligned.m16n8k8.row.col.f32.tf32.tf32.f32 "
                        "{%0,%1,%2,%3}, {%4,%5,%6,%7}, {%8,%9}, {%0,%1,%2,%3};\n"
                        : "+f"(c[0]), "+f"(c[1]), "+f"(c[2]), "+f"(c[3])
                        : "r"(af[mt][0]), "r"(af[mt][1]), "r"(af[mt][2]), "r"(af[mt][3]),
                          "r"(bf[nt][0]), "r"(bf[nt][1]));
                }
        }

        if (kc + 1 < NCHUNK) STORES(b ^ 1);
        __syncthreads();
    }

    // epilogue: d0 row=g col=2*la ; d1 col+1 ; d2 row=g+8 ; d3 col+1
    #pragma unroll
    for (int mt = 0; mt < 2; ++mt) {
        int r0 = rowBase + wm * 32 + mt * 16 + g;
        #pragma unroll
        for (int nt = 0; nt < 8; ++nt) {
            int col = wn * 64 + nt * 8 + la * 2;
            if (r0 < M)
                *(float2*)(g_xw + (size_t)r0 * HID + col) =
                    make_float2(acc[mt][nt][0], acc[mt][nt][1]);
            if (r0 + 8 < M)
                *(float2*)(g_xw + (size_t)(r0 + 8) * HID + col) =
                    make_float2(acc[mt][nt][2], acc[mt][nt][3]);
        }
    }
    #undef LOADG
    #undef STORES
}

// ================= SpMM1 (HID=128): warp per row + fused relu/bias/mask =====
__global__ __launch_bounds__(256) void spmm1_kernel(
    const int* __restrict__ src, const float* __restrict__ ew,
    const float* __restrict__ b1, const float* __restrict__ mask, int M)
{
    int gw = (blockIdx.x * blockDim.x + threadIdx.x) >> 5;
    int lane = threadIdx.x & 31;
    if (gw >= M) return;
    int start = g_rowstart[gw];
    int deg = g_counts[gw];
    float4 acc = make_float4(0.f, 0.f, 0.f, 0.f);

    for (int base = 0; base < deg; base += 32) {
        int rem = deg - base;
        int cnt = rem < 32 ? rem : 32;
        int s = 0; float w = 0.f;
        if (lane < cnt) {
            int e = g_perm[start + base + lane];
            s = src[e];
            w = ew[e];
        }
        for (int i = 0; i < cnt; ++i) {
            int   ss = __shfl_sync(0xffffffffu, s, i);
            float ww = __shfl_sync(0xffffffffu, w, i);
            float4 v = *(const float4*)(g_xw + (size_t)ss * HID + (lane << 2));
            acc.x = fmaf(ww, v.x, acc.x);
            acc.y = fmaf(ww, v.y, acc.y);
            acc.z = fmaf(ww, v.z, acc.z);
            acc.w = fmaf(ww, v.w, acc.w);
        }
    }

    float4 b = *(const float4*)(b1 + (lane << 2));
    float4 m = *(const float4*)(mask + (size_t)gw * HID + (lane << 2));
    float4 o;
    o.x = fmaxf(acc.x + b.x, 0.f) * m.x;
    o.y = fmaxf(acc.y + b.y, 0.f) * m.y;
    o.z = fmaxf(acc.z + b.z, 0.f) * m.z;
    o.w = fmaxf(acc.w + b.w, 0.f) * m.w;
    *(float4*)(g_h + (size_t)gw * HID + (lane << 2)) = o;
}

// ================= GEMM2: [M,128] @ [128,40] =================
__global__ __launch_bounds__(256) void gemm2_kernel(const float* __restrict__ W2, int M)
{
    __shared__ float Ws[HID][OUTF];   // 20 KB
    int tid = threadIdx.x;
    for (int i = tid; i < HID * OUTF; i += 256)
        Ws[i / OUTF][i % OUTF] = W2[i];
    __syncthreads();

    int r = blockIdx.x * 64 + (tid >> 2);
    int c0 = (tid & 3) * 10;
    if (r >= M) return;

    float acc[10] = {};
    const float4* hrow = (const float4*)(g_h + (size_t)r * HID);
    #pragma unroll 4
    for (int k4 = 0; k4 < HID / 4; ++k4) {
        float4 a = hrow[k4];
        int k = k4 * 4;
        #pragma unroll
        for (int j = 0; j < 10; ++j) acc[j] = fmaf(a.x, Ws[k + 0][c0 + j], acc[j]);
        #pragma unroll
        for (int j = 0; j < 10; ++j) acc[j] = fmaf(a.y, Ws[k + 1][c0 + j], acc[j]);
        #pragma unroll
        for (int j = 0; j < 10; ++j) acc[j] = fmaf(a.z, Ws[k + 2][c0 + j], acc[j]);
        #pragma unroll
        for (int j = 0; j < 10; ++j) acc[j] = fmaf(a.w, Ws[k + 3][c0 + j], acc[j]);
    }
    float* trow = g_t2 + (size_t)r * OUTF + c0;
    #pragma unroll
    for (int j = 0; j < 10; ++j) trow[j] = acc[j];
}

// ================= SpMM2 (OUT=40): warp per row + fused b2 =================
__global__ __launch_bounds__(256) void spmm2_kernel(
    const int* __restrict__ src, const float* __restrict__ ew,
    const float* __restrict__ b2, float* __restrict__ out, int M)
{
    int gw = (blockIdx.x * blockDim.x + threadIdx.x) >> 5;
    int lane = threadIdx.x & 31;
    if (gw >= M) return;
    int start = g_rowstart[gw];
    int deg = g_counts[gw];
    float2 acc = make_float2(0.f, 0.f);

    for (int base = 0; base < deg; base += 32) {
        int rem = deg - base;
        int cnt = rem < 32 ? rem : 32;
        int s = 0; float w = 0.f;
        if (lane < cnt) {
            int e = g_perm[start + base + lane];
            s = src[e];
            w = ew[e];
        }
        for (int i = 0; i < cnt; ++i) {
            int   ss = __shfl_sync(0xffffffffu, s, i);
            float ww = __shfl_sync(0xffffffffu, w, i);
            if (lane < 20) {
                float2 v = *(const float2*)(g_t2 + (size_t)ss * OUTF + (lane << 1));
                acc.x = fmaf(ww, v.x, acc.x);
                acc.y = fmaf(ww, v.y, acc.y);
            }
        }
    }

    if (lane < 20) {
        float2 b = *(const float2*)(b2 + (lane << 1));
        float2 o = make_float2(acc.x + b.x, acc.y + b.y);
        *(float2*)(out + (size_t)gw * OUTF + (lane << 1)) = o;
    }
}

// ================= launch =================
extern "C" void kernel_launch(void* const* d_in, const int* in_sizes, int n_in,
                              void* d_out, int out_size)
{
    const float* x    = (const float*)d_in[0];
    const float* W1   = (const float*)d_in[1];
    const float* b1   = (const float*)d_in[2];
    const float* W2   = (const float*)d_in[3];
    const float* b2   = (const float*)d_in[4];
    const float* ew   = (const float*)d_in[5];
    const float* mask = (const float*)d_in[6];
    const int*   esrc = (const int*)d_in[7];
    const int*   edst = (const int*)d_in[8];
    float* out = (float*)d_out;

    const int M = in_sizes[0] / F_IN;   // 50000
    const int E = in_sizes[7];          // 800000

    const int nbM = (M + 255) / 256;    // 196
    const int nbE = (E + 255) / 256;

    // CSR build (by destination)
    zero_counts_kernel<<<nbM, 256>>>(M);
    hist_kernel<<<nbE, 256>>>(edst, E);
    scanA_kernel<<<nbM, 256>>>(M);
    scanB_kernel<<<1, 256>>>(nbM);
    scanC_kernel<<<nbM, 256>>>(M);
    fill_perm_kernel<<<nbE, 256>>>(edst, E);

    // layer 1
    gemm1_tc_kernel<<<(M + 127) / 128, 256>>>(x, W1, M);
    spmm1_kernel<<<(M + 7) / 8, 256>>>(esrc, ew, b1, mask, M);

    // layer 2
    gemm2_kernel<<<(M + 63) / 64, 256>>>(W2, M);
    spmm2_kernel<<<(M + 7) / 8, 256>>>(esrc, ew, b2, out, M);
}

// round 5
// speedup vs baseline: 1.6826x; 1.0120x over previous
#include <cuda_runtime.h>
#include <cstdint>

#define F_IN 512
#define HID  128
#define OUTF 40
#define MAXN 50000
#define MAXE 800000
#define NTILE 256          // scan tile = 256 elements

// ---- device scratch (static; no allocation) ----
__device__ float g_xw[MAXN * HID];    // X @ W1
__device__ float g_h[MAXN * HID];     // hidden after spmm+relu+mask
__device__ float g_t2[MAXN * OUTF];   // h @ W2
__device__ int   g_counts[MAXN];
__device__ int   g_rowstart[MAXN];
__device__ int   g_cur[MAXN];
__device__ int2  g_edge[MAXE];        // (src, weight-bits) in CSR order
__device__ unsigned g_tstate[256];    // lookback state: (value<<2)|status
__device__ int   g_ticket;

// ================= CSR build =================
__global__ void zero_counts_kernel(int M) {
    int i = blockIdx.x * blockDim.x + threadIdx.x;
    if (i < M) g_counts[i] = 0;
    if (i < 256) g_tstate[i] = 0;
    if (i == 0) g_ticket = 0;
}

__global__ void hist_kernel(const int* __restrict__ dst, int E) {
    int e = blockIdx.x * blockDim.x + threadIdx.x;
    if (e < E) atomicAdd(&g_counts[dst[e]], 1);
}

// single-kernel exclusive scan over g_counts via decoupled lookback
__global__ void scan_kernel(int M) {
    __shared__ int s[NTILE];
    __shared__ int s_bid;
    __shared__ int s_prefix;
    int tid = threadIdx.x;
    if (tid == 0) s_bid = atomicAdd(&g_ticket, 1);
    __syncthreads();
    int bid = s_bid;
    int i = bid * NTILE + tid;
    int v = (i < M) ? g_counts[i] : 0;
    s[tid] = v;
    __syncthreads();
    #pragma unroll
    for (int off = 1; off < NTILE; off <<= 1) {
        int t = (tid >= off) ? s[tid - off] : 0;
        __syncthreads();
        s[tid] += t;
        __syncthreads();
    }
    if (tid == 0) {
        int agg = s[NTILE - 1];
        if (bid == 0) {
            atomicExch(&g_tstate[0], ((unsigned)agg << 2) | 2u);
            s_prefix = 0;
        } else {
            atomicExch(&g_tstate[bid], ((unsigned)agg << 2) | 1u);
            int run = 0;
            int j = bid - 1;
            while (true) {
                unsigned st;
                do { st = atomicOr(&g_tstate[j], 0u); } while ((st & 3u) == 0u);
                run += (int)(st >> 2);
                if ((st & 3u) == 2u) break;
                --j;
            }
            s_prefix = run;
            atomicExch(&g_tstate[bid], ((unsigned)(run + agg) << 2) | 2u);
        }
    }
    __syncthreads();
    if (i < M) {
        int excl = s_prefix + s[tid] - v;
        g_rowstart[i] = excl;
        g_cur[i] = excl;
    }
}

// fill CSR with (src, weight) pairs directly — no perm indirection later
__global__ void fill_kernel(const int* __restrict__ dst, const int* __restrict__ src,
                            const float* __restrict__ ew, int E) {
    int e = blockIdx.x * blockDim.x + threadIdx.x;
    if (e < E) {
        int p = atomicAdd(&g_cur[dst[e]], 1);
        g_edge[p] = make_int2(src[e], __float_as_int(ew[e]));
    }
}

// ================= GEMM1 (tensor cores, tf32) =================
__device__ __forceinline__ uint32_t f2tf(float f) {
    uint32_t u;
    asm("cvt.rna.tf32.f32 %0, %1;" : "=r"(u) : "f"(f));
    return u;
}

#define AS_STRIDE 20    // 16 k + 4 pad
#define BS_STRIDE 136   // 128 col + 8 pad

__global__ __launch_bounds__(256, 2) void gemm1_tc_kernel(
    const float* __restrict__ X, const float* __restrict__ W, int M)
{
    __shared__ uint32_t As[2][128 * AS_STRIDE];
    __shared__ uint32_t Bs[2][16 * BS_STRIDE];

    const int tid  = threadIdx.x;
    const int lane = tid & 31;
    const int wid  = tid >> 5;
    const int wm   = wid >> 1;
    const int wn   = wid & 1;
    const int g    = lane >> 2;
    const int la   = lane & 3;
    const int rowBase = blockIdx.x * 128;

    const int aRow = tid >> 2;
    const int aC4  = tid & 3;
    const int bK   = tid >> 5;
    const int bC4  = tid & 31;

    float acc[2][8][4];
    #pragma unroll
    for (int mt = 0; mt < 2; ++mt)
        #pragma unroll
        for (int nt = 0; nt < 8; ++nt)
            #pragma unroll
            for (int r = 0; r < 4; ++r) acc[mt][nt][r] = 0.f;

    float4 aL[2], bL[2];

    #define LOADG(kc) {                                                          \
        _Pragma("unroll")                                                        \
        for (int i = 0; i < 2; ++i) {                                            \
            int r = rowBase + aRow + i * 64;                                     \
            aL[i] = (r < M) ? *(const float4*)(X + (size_t)r * F_IN + (kc)*16 + aC4*4) \
                            : make_float4(0.f, 0.f, 0.f, 0.f);                   \
        }                                                                        \
        _Pragma("unroll")                                                        \
        for (int i = 0; i < 2; ++i) {                                            \
            int k = (kc)*16 + bK + i * 8;                                        \
            bL[i] = *(const float4*)(W + (size_t)k * HID + bC4 * 4);             \
        }                                                                        \
    }

    #define STORES(b) {                                                          \
        _Pragma("unroll")                                                        \
        for (int i = 0; i < 2; ++i) {                                            \
            uint4 u = make_uint4(f2tf(aL[i].x), f2tf(aL[i].y),                   \
                                 f2tf(aL[i].z), f2tf(aL[i].w));                  \
            *(uint4*)&As[b][(aRow + i * 64) * AS_STRIDE + aC4 * 4] = u;          \
        }                                                                        \
        _Pragma("unroll")                                                        \
        for (int i = 0; i < 2; ++i) {                                            \
            uint4 u = make_uint4(f2tf(bL[i].x), f2tf(bL[i].y),                   \
                                 f2tf(bL[i].z), f2tf(bL[i].w));                  \
            *(uint4*)&Bs[b][(bK + i * 8) * BS_STRIDE + bC4 * 4] = u;             \
        }                                                                        \
    }

    LOADG(0);
    STORES(0);
    __syncthreads();

    const int NCHUNK = F_IN / 16;
    for (int kc = 0; kc < NCHUNK; ++kc) {
        int b = kc & 1;
        if (kc + 1 < NCHUNK) LOADG(kc + 1);

        #pragma unroll
        for (int ks = 0; ks < 2; ++ks) {
            uint32_t af[2][4], bf[8][2];
            #pragma unroll
            for (int mt = 0; mt < 2; ++mt) {
                int rb = wm * 32 + mt * 16;
                af[mt][0] = As[b][(rb + g)     * AS_STRIDE + ks * 8 + la];
                af[mt][1] = As[b][(rb + 8 + g) * AS_STRIDE + ks * 8 + la];
                af[mt][2] = As[b][(rb + g)     * AS_STRIDE + ks * 8 + la + 4];
                af[mt][3] = As[b][(rb + 8 + g) * AS_STRIDE + ks * 8 + la + 4];
            }
            #pragma unroll
            for (int nt = 0; nt < 8; ++nt) {
                int col = wn * 64 + nt * 8 + g;
                bf[nt][0] = Bs[b][(ks * 8 + la)     * BS_STRIDE + col];
                bf[nt][1] = Bs[b][(ks * 8 + la + 4) * BS_STRIDE + col];
            }
            #pragma unroll
            for (int mt = 0; mt < 2; ++mt)
                #pragma unroll
                for (int nt = 0; nt < 8; ++nt) {
                    float* c = acc[mt][nt];
                    asm volatile(
                        "mma.sync.aligned.m16n8k8.row.col.f32.tf32.tf32.f32 "
                        "{%0,%1,%2,%3}, {%4,%5,%6,%7}, {%8,%9}, {%0,%1,%2,%3};\n"
                        : "+f"(c[0]), "+f"(c[1]), "+f"(c[2]), "+f"(c[3])
                        : "r"(af[mt][0]), "r"(af[mt][1]), "r"(af[mt][2]), "r"(af[mt][3]),
                          "r"(bf[nt][0]), "r"(bf[nt][1]));
                }
        }

        if (kc + 1 < NCHUNK) STORES(b ^ 1);
        __syncthreads();
    }

    #pragma unroll
    for (int mt = 0; mt < 2; ++mt) {
        int r0 = rowBase + wm * 32 + mt * 16 + g;
        #pragma unroll
        for (int nt = 0; nt < 8; ++nt) {
            int col = wn * 64 + nt * 8 + la * 2;
            if (r0 < M)
                *(float2*)(g_xw + (size_t)r0 * HID + col) =
                    make_float2(acc[mt][nt][0], acc[mt][nt][1]);
            if (r0 + 8 < M)
                *(float2*)(g_xw + (size_t)(r0 + 8) * HID + col) =
                    make_float2(acc[mt][nt][2], acc[mt][nt][3]);
        }
    }
    #undef LOADG
    #undef STORES
}

// ================= SpMM1 (HID=128): warp per row + fused relu/bias/mask =====
__global__ __launch_bounds__(256) void spmm1_kernel(
    const float* __restrict__ b1, const float* __restrict__ mask, int M)
{
    int gw = (blockIdx.x * blockDim.x + threadIdx.x) >> 5;
    int lane = threadIdx.x & 31;
    if (gw >= M) return;
    int start = g_rowstart[gw];
    int deg = g_counts[gw];
    float4 acc = make_float4(0.f, 0.f, 0.f, 0.f);

    for (int base = 0; base < deg; base += 32) {
        int rem = deg - base;
        int cnt = rem < 32 ? rem : 32;
        int s = 0; float w = 0.f;
        if (lane < cnt) {
            int2 ev = g_edge[start + base + lane];
            s = ev.x;
            w = __int_as_float(ev.y);
        }
        for (int i = 0; i < cnt; ++i) {
            int   ss = __shfl_sync(0xffffffffu, s, i);
            float ww = __shfl_sync(0xffffffffu, w, i);
            float4 v = *(const float4*)(g_xw + (size_t)ss * HID + (lane << 2));
            acc.x = fmaf(ww, v.x, acc.x);
            acc.y = fmaf(ww, v.y, acc.y);
            acc.z = fmaf(ww, v.z, acc.z);
            acc.w = fmaf(ww, v.w, acc.w);
        }
    }

    float4 b = *(const float4*)(b1 + (lane << 2));
    float4 m = *(const float4*)(mask + (size_t)gw * HID + (lane << 2));
    float4 o;
    o.x = fmaxf(acc.x + b.x, 0.f) * m.x;
    o.y = fmaxf(acc.y + b.y, 0.f) * m.y;
    o.z = fmaxf(acc.z + b.z, 0.f) * m.z;
    o.w = fmaxf(acc.w + b.w, 0.f) * m.w;
    *(float4*)(g_h + (size_t)gw * HID + (lane << 2)) = o;
}

// ================= GEMM2: [M,128] @ [128,40] =================
__global__ __launch_bounds__(256) void gemm2_kernel(const float* __restrict__ W2, int M)
{
    __shared__ float Ws[HID][OUTF];
    int tid = threadIdx.x;
    for (int i = tid; i < HID * OUTF; i += 256)
        Ws[i / OUTF][i % OUTF] = W2[i];
    __syncthreads();

    int r = blockIdx.x * 64 + (tid >> 2);
    int c0 = (tid & 3) * 10;
    if (r >= M) return;

    float acc[10] = {};
    const float4* hrow = (const float4*)(g_h + (size_t)r * HID);
    #pragma unroll 4
    for (int k4 = 0; k4 < HID / 4; ++k4) {
        float4 a = hrow[k4];
        int k = k4 * 4;
        #pragma unroll
        for (int j = 0; j < 10; ++j) acc[j] = fmaf(a.x, Ws[k + 0][c0 + j], acc[j]);
        #pragma unroll
        for (int j = 0; j < 10; ++j) acc[j] = fmaf(a.y, Ws[k + 1][c0 + j], acc[j]);
        #pragma unroll
        for (int j = 0; j < 10; ++j) acc[j] = fmaf(a.z, Ws[k + 2][c0 + j], acc[j]);
        #pragma unroll
        for (int j = 0; j < 10; ++j) acc[j] = fmaf(a.w, Ws[k + 3][c0 + j], acc[j]);
    }
    float* trow = g_t2 + (size_t)r * OUTF + c0;
    #pragma unroll
    for (int j = 0; j < 10; ++j) trow[j] = acc[j];
}

// ================= SpMM2 (OUT=40): warp per row + fused b2 =================
__global__ __launch_bounds__(256) void spmm2_kernel(
    const float* __restrict__ b2, float* __restrict__ out, int M)
{
    int gw = (blockIdx.x * blockDim.x + threadIdx.x) >> 5;
    int lane = threadIdx.x & 31;
    if (gw >= M) return;
    int start = g_rowstart[gw];
    int deg = g_counts[gw];
    float2 acc = make_float2(0.f, 0.f);

    for (int base = 0; base < deg; base += 32) {
        int rem = deg - base;
        int cnt = rem < 32 ? rem : 32;
        int s = 0; float w = 0.f;
        if (lane < cnt) {
            int2 ev = g_edge[start + base + lane];
            s = ev.x;
            w = __int_as_float(ev.y);
        }
        for (int i = 0; i < cnt; ++i) {
            int   ss = __shfl_sync(0xffffffffu, s, i);
            float ww = __shfl_sync(0xffffffffu, w, i);
            if (lane < 20) {
                float2 v = *(const float2*)(g_t2 + (size_t)ss * OUTF + (lane << 1));
                acc.x = fmaf(ww, v.x, acc.x);
                acc.y = fmaf(ww, v.y, acc.y);
            }
        }
    }

    if (lane < 20) {
        float2 b = *(const float2*)(b2 + (lane << 1));
        float2 o = make_float2(acc.x + b.x, acc.y + b.y);
        *(float2*)(out + (size_t)gw * OUTF + (lane << 1)) = o;
    }
}

// ================= launch =================
extern "C" void kernel_launch(void* const* d_in, const int* in_sizes, int n_in,
                              void* d_out, int out_size)
{
    const float* x    = (const float*)d_in[0];
    const float* W1   = (const float*)d_in[1];
    const float* b1   = (const float*)d_in[2];
    const float* W2   = (const float*)d_in[3];
    const float* b2   = (const float*)d_in[4];
    const float* ew   = (const float*)d_in[5];
    const float* mask = (const float*)d_in[6];
    const int*   esrc = (const int*)d_in[7];
    const int*   edst = (const int*)d_in[8];
    float* out = (float*)d_out;

    const int M = in_sizes[0] / F_IN;   // 50000
    const int E = in_sizes[7];          // 800000

    const int nbM = (M + NTILE - 1) / NTILE;   // 196
    const int nbE = (E + 255) / 256;

    // CSR build (by destination): 4 launches
    zero_counts_kernel<<<nbM, 256>>>(M);
    hist_kernel<<<nbE, 256>>>(edst, E);
    scan_kernel<<<nbM, NTILE>>>(M);
    fill_kernel<<<nbE, 256>>>(edst, esrc, ew, E);

    // layer 1
    gemm1_tc_kernel<<<(M + 127) / 128, 256>>>(x, W1, M);
    spmm1_kernel<<<(M + 7) / 8, 256>>>(b1, mask, M);

    // layer 2
    gemm2_kernel<<<(M + 63) / 64, 256>>>(W2, M);
    spmm2_kernel<<<(M + 7) / 8, 256>>>(b2, out, M);
}